// round 4
// baseline (speedup 1.0000x reference)
#include <cuda_runtime.h>

#define BB   4
#define TQ   256
#define TV   2048
#define DD   512
#define UU   128
#define NROWS_Q (BB*TQ)          // 1024
#define NROWS_K (BB*TV)          // 8192
#define CTX_SIZE (NROWS_Q*UU)    // 131072
#define WTS_SIZE (NROWS_Q*TV)    // 2097152

// Scratch (no cudaMalloc allowed)
__device__ float g_q[NROWS_Q*UU];        // 0.5 MB
__device__ float g_k[NROWS_K*UU];        // 4 MB
__device__ float g_scores[NROWS_Q*TV];   // 8 MB
__device__ float g_part[4][CTX_SIZE];    // 2 MB

__device__ __forceinline__ float ex2f_(float x){ float y; asm("ex2.approx.f32 %0, %1;" : "=f"(y) : "f"(x)); return y; }
__device__ __forceinline__ float rcpf_(float x){ float y; asm("rcp.approx.f32 %0, %1;" : "=f"(y) : "f"(x)); return y; }

// ---------------------------------------------------------------------------
// Kernel 1: projections. C[M,128] = A[M,512] @ W[512,128], fp32.
// bid<16 -> q (M=1024), else -> k (M=8192). BM=64, BN=128, BK=16, tile 4x8.
// ---------------------------------------------------------------------------
__global__ __launch_bounds__(256) void proj_gemm(
    const float* __restrict__ dq, const float* __restrict__ ev,
    const float* __restrict__ W1, const float* __restrict__ W2)
{
    __shared__ float As[16][68];    // [kk][m], padded
    __shared__ float Bs[16][128];   // [kk][n]

    int bid = blockIdx.x;
    const float* A; const float* W; float* C; int mbase;
    if (bid < 16) { A = dq; W = W1; C = g_q; mbase = bid * 64; }
    else          { A = ev; W = W2; C = g_k; mbase = (bid - 16) * 64; }

    int t  = threadIdx.x;
    int ty = t >> 4;          // 0..15 (row group)
    int tx = t & 15;          // 0..15 (col group)
    int lr = t >> 2;          // 0..63 (A load row)
    int lc = (t & 3) << 2;    // 0,4,8,12 (A load col quad)

    float acc[4][8];
    #pragma unroll
    for (int i = 0; i < 4; i++)
        #pragma unroll
        for (int j = 0; j < 8; j++) acc[i][j] = 0.0f;

    for (int k0 = 0; k0 < DD; k0 += 16) {
        float4 av = *(const float4*)&A[(size_t)(mbase + lr) * DD + k0 + lc];
        As[lc + 0][lr] = av.x; As[lc + 1][lr] = av.y;
        As[lc + 2][lr] = av.z; As[lc + 3][lr] = av.w;
        {
            int i0 = t, i1 = t + 256;
            *(float4*)&Bs[i0 >> 5][(i0 & 31) << 2] =
                *(const float4*)&W[(size_t)(k0 + (i0 >> 5)) * UU + ((i0 & 31) << 2)];
            *(float4*)&Bs[i1 >> 5][(i1 & 31) << 2] =
                *(const float4*)&W[(size_t)(k0 + (i1 >> 5)) * UU + ((i1 & 31) << 2)];
        }
        __syncthreads();

        #pragma unroll
        for (int kk = 0; kk < 16; kk++) {
            float4 a4 = *(const float4*)&As[kk][ty * 4];
            float4 b0 = *(const float4*)&Bs[kk][tx * 4];
            float4 b1 = *(const float4*)&Bs[kk][64 + tx * 4];
            float a[4] = {a4.x, a4.y, a4.z, a4.w};
            float b[8] = {b0.x, b0.y, b0.z, b0.w, b1.x, b1.y, b1.z, b1.w};
            #pragma unroll
            for (int i = 0; i < 4; i++)
                #pragma unroll
                for (int j = 0; j < 8; j++)
                    acc[i][j] = fmaf(a[i], b[j], acc[i][j]);
        }
        __syncthreads();
    }

    #pragma unroll
    for (int i = 0; i < 4; i++) {
        int row = mbase + ty * 4 + i;
        *(float4*)&C[(size_t)row * UU + tx * 4] =
            make_float4(acc[i][0], acc[i][1], acc[i][2], acc[i][3]);
        *(float4*)&C[(size_t)row * UU + 64 + tx * 4] =
            make_float4(acc[i][4], acc[i][5], acc[i][6], acc[i][7]);
    }
}

// ---------------------------------------------------------------------------
// Kernel 2: scores[b,q,v] = sum_u scale[u] * tanh(q[b,q,u] + k[b,v,u])
// Block tile: 16 q x 64 v, full U=128 in smem. Thread: 4 q x 1 v.
// tanh(x) = 1 - 2/(exp(2x)+1) via ex2.approx + rcp.approx (rel err ~1e-6).
// ---------------------------------------------------------------------------
__global__ __launch_bounds__(256) void scores_kernel(const float* __restrict__ scale)
{
    __shared__ __align__(16) float Qs[16][136];  // 136-float stride: 16B-aligned rows, <=2-way LDS conflicts
    __shared__ __align__(16) float Ks[64][136];
    __shared__ __align__(16) float Ss[128];

    int b  = blockIdx.z;
    int qt = blockIdx.y;
    int vt = blockIdx.x;
    int t  = threadIdx.x;

    const float* qg = g_q + (size_t)(b * TQ + qt * 16) * UU;
    const float* kg = g_k + (size_t)(b * TV + vt * 64) * UU;

    #pragma unroll
    for (int j = 0; j < 2; j++) {
        int i = t + j * 256;
        int r = i >> 5, c = (i & 31) << 2;
        *(float4*)&Qs[r][c] = *(const float4*)&qg[(size_t)r * UU + c];
    }
    #pragma unroll
    for (int j = 0; j < 8; j++) {
        int i = t + j * 256;
        int r = i >> 5, c = (i & 31) << 2;
        *(float4*)&Ks[r][c] = *(const float4*)&kg[(size_t)r * UU + c];
    }
    if (t < 32) *(float4*)&Ss[t * 4] = *(const float4*)&scale[t * 4];
    __syncthreads();

    int v   = t & 63;    // consecutive lanes -> consecutive K rows
    int qg4 = t >> 6;    // 0..3 -> q rows qg4*4 .. +3

    const float4* K4 = (const float4*)&Ks[v][0];
    const float4* S4 = (const float4*)&Ss[0];

    float acc[4] = {0.0f, 0.0f, 0.0f, 0.0f};
    const float C2 = 2.88539008177792681f;   // 2*log2(e)

    #pragma unroll 8
    for (int uc = 0; uc < 32; uc++) {
        float4 kv = K4[uc];
        float4 sv = S4[uc];
        #pragma unroll
        for (int i = 0; i < 4; i++) {
            float4 qv = *(const float4*)&Qs[qg4 * 4 + i][uc * 4];
            float s = acc[i];
            { float x = qv.x + kv.x; float e = ex2f_(x * C2); float r = rcpf_(e + 1.0f);
              s = fmaf(sv.x, fmaf(-2.0f, r, 1.0f), s); }
            { float x = qv.y + kv.y; float e = ex2f_(x * C2); float r = rcpf_(e + 1.0f);
              s = fmaf(sv.y, fmaf(-2.0f, r, 1.0f), s); }
            { float x = qv.z + kv.z; float e = ex2f_(x * C2); float r = rcpf_(e + 1.0f);
              s = fmaf(sv.z, fmaf(-2.0f, r, 1.0f), s); }
            { float x = qv.w + kv.w; float e = ex2f_(x * C2); float r = rcpf_(e + 1.0f);
              s = fmaf(sv.w, fmaf(-2.0f, r, 1.0f), s); }
            acc[i] = s;
        }
    }

    float* out = g_scores + (size_t)(b * TQ + qt * 16 + qg4 * 4) * TV + vt * 64 + v;
    out[0]      = acc[0];
    out[TV]     = acc[1];
    out[2 * TV] = acc[2];
    out[3 * TV] = acc[3];
}

// ---------------------------------------------------------------------------
// Kernel 3: row softmax over Tv=2048. One block per (b,q) row.
// Writes weights into d_out (after the context region).
// ---------------------------------------------------------------------------
__global__ __launch_bounds__(256) void softmax_kernel(float* __restrict__ wout)
{
    __shared__ float red[8];
    int row = blockIdx.x;
    int t   = threadIdx.x;

    const float4* in4 = (const float4*)(g_scores + (size_t)row * TV);
    float4 a = in4[t];
    float4 b = in4[t + 256];

    float m = fmaxf(fmaxf(fmaxf(a.x, a.y), fmaxf(a.z, a.w)),
                    fmaxf(fmaxf(b.x, b.y), fmaxf(b.z, b.w)));
    #pragma unroll
    for (int off = 16; off; off >>= 1)
        m = fmaxf(m, __shfl_xor_sync(0xffffffffu, m, off));
    if ((t & 31) == 0) red[t >> 5] = m;
    __syncthreads();
    m = red[0];
    #pragma unroll
    for (int i = 1; i < 8; i++) m = fmaxf(m, red[i]);

    const float L2E = 1.44269504088896341f;
    float e0 = ex2f_((a.x - m) * L2E), e1 = ex2f_((a.y - m) * L2E);
    float e2 = ex2f_((a.z - m) * L2E), e3 = ex2f_((a.w - m) * L2E);
    float e4 = ex2f_((b.x - m) * L2E), e5 = ex2f_((b.y - m) * L2E);
    float e6 = ex2f_((b.z - m) * L2E), e7 = ex2f_((b.w - m) * L2E);
    float s = ((e0 + e1) + (e2 + e3)) + ((e4 + e5) + (e6 + e7));
    #pragma unroll
    for (int off = 16; off; off >>= 1)
        s += __shfl_xor_sync(0xffffffffu, s, off);
    __syncthreads();                       // red reads above done
    if ((t & 31) == 0) red[t >> 5] = s;
    __syncthreads();
    float tot = 0.0f;
    #pragma unroll
    for (int i = 0; i < 8; i++) tot += red[i];
    float inv = rcpf_(tot);

    float4* o4 = (float4*)(wout + (size_t)row * TV);
    o4[t]       = make_float4(e0 * inv, e1 * inv, e2 * inv, e3 * inv);
    o4[t + 256] = make_float4(e4 * inv, e5 * inv, e6 * inv, e7 * inv);
}

// ---------------------------------------------------------------------------
// Kernel 4: context partials. ctx[b,q,u] = sum_v w[b,q,v]*k[b,v,u].
// Grid (4 v-chunks, 64 row-tiles of 16). 128 threads = one per u.
// ---------------------------------------------------------------------------
__global__ __launch_bounds__(128) void ctx_partial(const float* __restrict__ wts)
{
    __shared__ float Ks2[64][128];
    __shared__ float Wst[64][20];   // [v][q], padded stride 20 (16B-aligned rows)

    int chunk = blockIdx.x;          // 0..3 -> v in [chunk*512, +512)
    int rt    = blockIdx.y;          // 0..63
    int r0    = rt * 16;             // global row base (b*256+q)
    int bbb   = r0 >> 8;             // batch
    int t     = threadIdx.x;         // u

    float acc[16];
    #pragma unroll
    for (int q = 0; q < 16; q++) acc[q] = 0.0f;

    for (int vt = 0; vt < 8; vt++) {
        int vbase = chunk * 512 + vt * 64;
        #pragma unroll
        for (int j = 0; j < 16; j++) {
            int i = t + j * 128;
            int v = i >> 5, c = (i & 31) << 2;
            *(float4*)&Ks2[v][c] =
                *(const float4*)&g_k[(size_t)(bbb * TV + vbase + v) * UU + c];
        }
        #pragma unroll
        for (int j = 0; j < 8; j++) {
            int i = t + j * 128;
            int q = i >> 6, v = i & 63;
            Wst[v][q] = wts[(size_t)(r0 + q) * TV + vbase + v];
        }
        __syncthreads();

        #pragma unroll 4
        for (int v = 0; v < 64; v++) {
            float kv  = Ks2[v][t];
            float4 w0 = *(const float4*)&Wst[v][0];
            float4 w1 = *(const float4*)&Wst[v][4];
            float4 w2 = *(const float4*)&Wst[v][8];
            float4 w3 = *(const float4*)&Wst[v][12];
            acc[0]  = fmaf(w0.x, kv, acc[0]);  acc[1]  = fmaf(w0.y, kv, acc[1]);
            acc[2]  = fmaf(w0.z, kv, acc[2]);  acc[3]  = fmaf(w0.w, kv, acc[3]);
            acc[4]  = fmaf(w1.x, kv, acc[4]);  acc[5]  = fmaf(w1.y, kv, acc[5]);
            acc[6]  = fmaf(w1.z, kv, acc[6]);  acc[7]  = fmaf(w1.w, kv, acc[7]);
            acc[8]  = fmaf(w2.x, kv, acc[8]);  acc[9]  = fmaf(w2.y, kv, acc[9]);
            acc[10] = fmaf(w2.z, kv, acc[10]); acc[11] = fmaf(w2.w, kv, acc[11]);
            acc[12] = fmaf(w3.x, kv, acc[12]); acc[13] = fmaf(w3.y, kv, acc[13]);
            acc[14] = fmaf(w3.z, kv, acc[14]); acc[15] = fmaf(w3.w, kv, acc[15]);
        }
        __syncthreads();
    }

    #pragma unroll
    for (int q = 0; q < 16; q++)
        g_part[chunk][(size_t)(r0 + q) * UU + t] = acc[q];
}

// ---------------------------------------------------------------------------
// Kernel 5: reduce 4 partials -> context into d_out[0 .. CTX_SIZE)
// ---------------------------------------------------------------------------
__global__ __launch_bounds__(256) void ctx_reduce(float* __restrict__ out)
{
    int i = blockIdx.x * 256 + threadIdx.x;   // float4 index, 32768 total
    const float4* p0 = (const float4*)g_part[0];
    const float4* p1 = (const float4*)g_part[1];
    const float4* p2 = (const float4*)g_part[2];
    const float4* p3 = (const float4*)g_part[3];
    float4 a = p0[i], b = p1[i], c = p2[i], d = p3[i];
    ((float4*)out)[i] = make_float4(a.x + b.x + c.x + d.x,
                                    a.y + b.y + c.y + d.y,
                                    a.z + b.z + c.z + d.z,
                                    a.w + b.w + c.w + d.w);
}

extern "C" void kernel_launch(void* const* d_in, const int* in_sizes, int n_in,
                              void* d_out, int out_size)
{
    (void)in_sizes; (void)n_in; (void)out_size;
    const float* dq    = (const float*)d_in[0];   // [4,256,512]
    const float* ev    = (const float*)d_in[1];   // [4,2048,512]
    const float* W1    = (const float*)d_in[2];   // [512,128]
    const float* W2    = (const float*)d_in[3];   // [512,128]
    const float* scale = (const float*)d_in[4];   // [128]
    float* out = (float*)d_out;                   // context [131072] ++ weights [2097152]
    float* wout = out + CTX_SIZE;

    proj_gemm<<<144, 256>>>(dq, ev, W1, W2);
    scores_kernel<<<dim3(TV / 64, TQ / 16, BB), 256>>>(scale);
    softmax_kernel<<<NROWS_Q, 256>>>(wout);
    ctx_partial<<<dim3(4, 64), 128>>>(wout);
    ctx_reduce<<<CTX_SIZE / 4 / 256, 256>>>(out);
}